// round 1
// baseline (speedup 1.0000x reference)
#include <cuda_runtime.h>

typedef unsigned long long ull;

#define BB 4
#define HH 224
#define WL 224
#define HW 50176
#define NC 64
#define EE 768
#define SS 256

// ---- scratch (static device allocations; no cudaMalloc allowed) ----
__device__ float g_buf1[BB*NC*HW];   // conv1 output  (51.4 MB)
__device__ float g_buf2[BB*NC*HW];   // conv2 output  (51.4 MB)
__device__ int   g_cnt[BB*SS];
__device__ int   g_off[BB*SS];
__device__ int   g_cur[BB*SS];
__device__ int   g_order[BB*HW];

// ---- packed fp32x2 helpers (sm_100+) ----
__device__ __forceinline__ ull pack2(float a, float b){
    ull d; asm("mov.b64 %0,{%1,%2};" : "=l"(d) : "f"(a), "f"(b)); return d;
}
__device__ __forceinline__ void ffma2(ull& d, ull a, ull b){
    asm("fma.rn.f32x2 %0,%1,%2,%0;" : "+l"(d) : "l"(a), "l"(b));
}
__device__ __forceinline__ float2 unpack2(ull d){
    float2 f; asm("mov.b64 {%0,%1},%2;" : "=f"(f.x), "=f"(f.y) : "l"(d)); return f;
}

// ================= zero counters (re-zero every launch / graph replay) ======
__global__ void k_zero(){
    int t = threadIdx.x;   // 1024 threads == BB*SS
    g_cnt[t] = 0; g_cur[t] = 0;
}

// ================= conv1: 3->64, 3x3 SAME, relu =============================
__global__ __launch_bounds__(256) void k_conv1(const float* __restrict__ img,
                                               const float* __restrict__ w1){
    __shared__ float ws[64*27];
    int tid = threadIdx.x;
    for (int i = tid; i < 64*27; i += 256) ws[i] = w1[i];
    __syncthreads();
    int b = blockIdx.y;
    int p = blockIdx.x*256 + tid;
    int y = p / WL, x = p % WL;
    float v[27];
#pragma unroll
    for (int ci = 0; ci < 3; ci++)
#pragma unroll
    for (int ky = 0; ky < 3; ky++)
#pragma unroll
    for (int kx = 0; kx < 3; kx++){
        int yy = y + ky - 1, xx = x + kx - 1;
        float val = 0.f;
        if (yy >= 0 && yy < HH && xx >= 0 && xx < WL)
            val = img[(size_t)(b*3+ci)*HW + yy*WL + xx];
        v[ci*9 + ky*3 + kx] = val;
    }
#pragma unroll 4
    for (int co = 0; co < 64; co++){
        float a = 0.f;
#pragma unroll
        for (int t = 0; t < 27; t++) a = fmaf(ws[co*27+t], v[t], a);
        g_buf1[(size_t)(b*64+co)*HW + p] = fmaxf(a, 0.f);
    }
}

// ================= conv2: 64->64, 3x3 SAME, relu ============================
// CTA tile: 8y x 32x pixels, all 64 co. thread = 8 px (4 f32x2 pairs) x 8 co.
__global__ __launch_bounds__(256) void k_conv2(const float* __restrict__ w2){
    __shared__ float ins[8][10][35];      // [ci][row][col] padded stride 35
    __shared__ ull   wsh[8][9][64];       // [ci][k][co], (w,w) duplicated
    int tid = threadIdx.x;
    int b  = blockIdx.z;
    int x0 = blockIdx.x*32, y0 = blockIdx.y*8;
    int cog = tid >> 5;           // warp id -> co group (broadcast weight LDS)
    int r   = tid & 31;
    int ty  = r >> 2;             // 0..7
    int xl0 = (r & 3) * 8;        // 0,8,16,24

    ull acc[8][4];
#pragma unroll
    for (int c = 0; c < 8; c++)
#pragma unroll
    for (int q = 0; q < 4; q++) acc[c][q] = 0ULL;

    for (int cc = 0; cc < 8; cc++){
        // stage input tile (with halo, zero padded)
        for (int lin = tid; lin < 2720; lin += 256){
            int ci = lin / 340, rem = lin % 340;
            int rr = rem / 34, ccol = rem % 34;
            int gy = y0 + rr - 1, gx = x0 + ccol - 1;
            float v = 0.f;
            if (gy >= 0 && gy < HH && gx >= 0 && gx < WL)
                v = g_buf1[(size_t)(b*64 + cc*8 + ci)*HW + gy*WL + gx];
            ins[ci][rr][ccol] = v;
        }
        // stage weights, duplicated into f32x2 pairs
        for (int lin = tid; lin < 4608; lin += 256){
            int co = lin / 72, rem = lin % 72;
            int ci = rem / 9, k = rem % 9;
            float v = w2[co*576 + (cc*8+ci)*9 + k];
            wsh[ci][k][co] = pack2(v, v);
        }
        __syncthreads();
#pragma unroll 2
        for (int ci = 0; ci < 8; ci++){
#pragma unroll
            for (int ky = 0; ky < 3; ky++){
                float a[10];
#pragma unroll
                for (int m = 0; m < 10; m++) a[m] = ins[ci][ty+ky][xl0+m];
                ull P[9];
#pragma unroll
                for (int m = 0; m < 9; m++) P[m] = pack2(a[m], a[m+1]);
#pragma unroll
                for (int kx = 0; kx < 3; kx++){
#pragma unroll
                    for (int c = 0; c < 8; c++){
                        ull w = wsh[ci][ky*3+kx][cog*8+c];
                        ffma2(acc[c][0], P[kx+0], w);
                        ffma2(acc[c][1], P[kx+2], w);
                        ffma2(acc[c][2], P[kx+4], w);
                        ffma2(acc[c][3], P[kx+6], w);
                    }
                }
            }
        }
        __syncthreads();
    }
    int y = y0 + ty;
#pragma unroll
    for (int c = 0; c < 8; c++){
        int co = cog*8 + c;
        float* outp = &g_buf2[(size_t)(b*64+co)*HW + y*WL + x0 + xl0];
#pragma unroll
        for (int q = 0; q < 4; q++){
            float2 v = unpack2(acc[c][q]);
            v.x = fmaxf(v.x, 0.f); v.y = fmaxf(v.y, 0.f);
            *(float2*)(outp + 2*q) = v;
        }
    }
}

// ================= segment counting sort =====================================
__global__ __launch_bounds__(256) void k_hist(const int* __restrict__ seg){
    __shared__ int hist[SS];
    int tid = threadIdx.x;
    hist[tid] = 0;
    __syncthreads();
    int b = blockIdx.y;
    int base = blockIdx.x * 1024;
#pragma unroll
    for (int i = 0; i < 4; i++){
        int s = seg[(size_t)b*HW + base + i*256 + tid];
        atomicAdd(&hist[s], 1);
    }
    __syncthreads();
    atomicAdd(&g_cnt[b*SS + tid], hist[tid]);
}

__global__ void k_scan(){                 // 1 CTA, 1024 threads
    __shared__ int s[1024];
    int t = threadIdx.x;
    int v = g_cnt[t];
    s[t] = v;
    __syncthreads();
    for (int d = 1; d < 1024; d <<= 1){
        int add = (t >= d) ? s[t-d] : 0;
        __syncthreads();
        s[t] += add;
        __syncthreads();
    }
    g_off[t] = s[t] - v;                  // exclusive prefix
}

__global__ __launch_bounds__(256) void k_scatter(const int* __restrict__ seg){
    int b = blockIdx.y;
    int p = blockIdx.x*256 + threadIdx.x;
    int sgm = seg[(size_t)b*HW + p];
    int bin = b*SS + sgm;
    int idx = atomicAdd(&g_cur[bin], 1);
    g_order[g_off[bin] + idx] = p;
}

// ================= conv3 (1x1, 64->768, relu) fused with mean pooling =======
// One CTA per (batch,segment). 384 threads x 2 e's. Weights live in registers
// as 64 packed (w[e0],w[e1]) pairs. Features staged per 64-pixel sub-batch
// into smem as duplicated f32x2. Atomic-free: register accumulation + divide.
__global__ __launch_bounds__(384, 1) void k_conv3pool(const float* __restrict__ w3,
                                                      float* __restrict__ out){
    __shared__ ull fs[64][64];            // [ci][px], (f,f) duplicated
    __shared__ int pixsm[64];
    int tid = threadIdx.x;
    int bin = blockIdx.x;
    int b = bin >> 8;
    int npix = g_cnt[bin];
    int off  = g_off[bin];
    const float* fbase = g_buf2 + (size_t)b*64*HW;

    int e0 = 2*tid;
    ull wr[64];
    const float4* w3a = (const float4*)(w3 + (size_t)e0*64);
    const float4* w3b = (const float4*)(w3 + (size_t)(e0+1)*64);
#pragma unroll
    for (int g = 0; g < 16; g++){
        float4 fa = w3a[g], fb = w3b[g];
        wr[4*g+0] = pack2(fa.x, fb.x);
        wr[4*g+1] = pack2(fa.y, fb.y);
        wr[4*g+2] = pack2(fa.z, fb.z);
        wr[4*g+3] = pack2(fa.w, fb.w);
    }
    float oa0 = 0.f, oa1 = 0.f;
    for (int pb = 0; pb < npix; pb += 64){
        int rem = npix - pb; if (rem > 64) rem = 64;
        if (tid < 64) pixsm[tid] = (tid < rem) ? g_order[off + pb + tid] : 0;
        __syncthreads();
        for (int lin = tid; lin < 4096; lin += 384){
            int ci = lin >> 6, px = lin & 63;
            float v = 0.f;
            if (px < rem) v = fbase[(size_t)ci*HW + pixsm[px]];
            fs[ci][px] = pack2(v, v);
        }
        __syncthreads();
        for (int px = 0; px < rem; px++){
            ull s0 = 0ULL, s1 = 0ULL;
#pragma unroll
            for (int ci = 0; ci < 64; ci += 2){
                ffma2(s0, fs[ci][px],   wr[ci]);
                ffma2(s1, fs[ci+1][px], wr[ci+1]);
            }
            float2 fa = unpack2(s0), fb = unpack2(s1);
            oa0 += fmaxf(fa.x + fb.x, 0.f);
            oa1 += fmaxf(fa.y + fb.y, 0.f);
        }
        __syncthreads();
    }
    float inv = 1.f / (float)max(npix, 1);
    float2 o; o.x = oa0*inv; o.y = oa1*inv;
    *(float2*)(out + (size_t)bin*EE + e0) = o;
}

// ================= positional MLP ===========================================
// CTA = 16 rows of (b,s). h staged in smem as [j][16 rows]; f32x2 over row pairs.
__global__ __launch_bounds__(256) void k_pos(const float* __restrict__ cent,
        const float* __restrict__ w1, const float* __restrict__ b1,
        const float* __restrict__ w2, const float* __restrict__ b2,
        float* __restrict__ out){
    __shared__ __align__(8) float h2[384*16];
    int tid = threadIdx.x;
    int rb = blockIdx.x * 16;
    for (int lin = tid; lin < 6144; lin += 256){
        int j = lin >> 4, r = lin & 15;
        int rid = rb + r;
        float c0 = cent[rid*2+0] * (1.f/223.f);
        float c1 = cent[rid*2+1] * (1.f/223.f);
        float h = fmaxf(fmaf(c0, w1[j], fmaf(c1, w1[384+j], b1[j])), 0.f);
        h2[j*16 + r] = h;
    }
    __syncthreads();
    ull acc[3][8];
#pragma unroll
    for (int es = 0; es < 3; es++)
#pragma unroll
    for (int q = 0; q < 8; q++) acc[es][q] = 0ULL;
    for (int j = 0; j < 384; j++){
        ull hp[8];
#pragma unroll
        for (int q = 0; q < 8; q++) hp[q] = *(const ull*)&h2[j*16 + 2*q];
#pragma unroll
        for (int es = 0; es < 3; es++){
            float wv = w2[j*768 + tid + es*256];
            ull wp = pack2(wv, wv);
#pragma unroll
            for (int q = 0; q < 8; q++) ffma2(acc[es][q], hp[q], wp);
        }
    }
#pragma unroll
    for (int es = 0; es < 3; es++){
        int e = tid + es*256;
        float bv = b2[e];
#pragma unroll
        for (int q = 0; q < 8; q++){
            float2 v = unpack2(acc[es][q]);
            int rid = rb + 2*q;
            out[(size_t)rid*768 + e]     = v.x + bv;
            out[(size_t)(rid+1)*768 + e] = v.y + bv;
        }
    }
}

// ================= launcher =================================================
extern "C" void kernel_launch(void* const* d_in, const int* in_sizes, int n_in,
                              void* d_out, int out_size){
    const float* img  = (const float*)d_in[0];
    const int*   seg  = (const int*)d_in[1];
    const float* cent = (const float*)d_in[2];
    const float* w1   = (const float*)d_in[3];
    const float* w2   = (const float*)d_in[4];
    const float* w3   = (const float*)d_in[5];
    const float* pw1  = (const float*)d_in[6];
    const float* pb1  = (const float*)d_in[7];
    const float* pw2  = (const float*)d_in[8];
    const float* pb2  = (const float*)d_in[9];
    float* out = (float*)d_out;

    k_zero<<<1, 1024>>>();
    k_conv1<<<dim3(196,4), 256>>>(img, w1);
    k_conv2<<<dim3(7,28,4), 256>>>(w2);
    k_hist<<<dim3(49,4), 256>>>(seg);
    k_scan<<<1, 1024>>>();
    k_scatter<<<dim3(196,4), 256>>>(seg);
    k_conv3pool<<<BB*SS, 384>>>(w3, out);
    k_pos<<<64, 256>>>(cent, pw1, pb1, pw2, pb2, out + (size_t)BB*SS*EE);
}